// round 5
// baseline (speedup 1.0000x reference)
#include <cuda_runtime.h>

#define NMAX 50000
#define EMAX 700000

// Scratch (allocation-free: __device__ globals)
__device__ float g_dinv[NMAX];
__device__ float g_bufA[(size_t)NMAX * 128];
__device__ float g_bufB[(size_t)NMAX * 128];
__device__ int   g_cnt[NMAX];
__device__ int   g_incl[NMAX];
__device__ int   g_bsum[256];
__device__ int   g_off[NMAX + 1];
__device__ int   g_cursor[NMAX];
__device__ int   g_srcid[EMAX];
__device__ float g_srcdn[EMAX];
__device__ int   g_is64;

// ---------------------------------------------------------------------------
// edge_index dtype detection (int64 vs int32, see prior rounds)
// ---------------------------------------------------------------------------
__global__ void detect_dtype_kernel(const int* __restrict__ ei) {
    if (threadIdx.x == 0) {
        int nz = 0;
        for (int i = 1; i < 256; i += 2) nz |= (ei[i] != 0);
        g_is64 = nz ? 0 : 1;
    }
}

__device__ __forceinline__ void load_edge(const void* ei, int E, int e, int& r, int& c) {
    if (g_is64) {
        const long long* p = (const long long*)ei;
        r = (int)p[e];
        c = (int)p[(size_t)E + e];
    } else {
        const int* p = (const int*)ei;
        r = p[e];
        c = p[E + e];
    }
}

// ---------------------------------------------------------------------------
// CSR build: counting sort of edges by destination (col), self-loops included.
// ---------------------------------------------------------------------------
__global__ void cnt_init_kernel(int* cnt, int n) {
    int i = blockIdx.x * blockDim.x + threadIdx.x;
    if (i < n) cnt[i] = 1;  // self-loop
}

__global__ void cnt_count_kernel(int* cnt, const void* __restrict__ ei, int E) {
    int e = blockIdx.x * blockDim.x + threadIdx.x;
    if (e >= E) return;
    int c;
    if (g_is64) c = (int)((const long long*)ei)[(size_t)E + e];
    else        c = ((const int*)ei)[E + e];
    atomicAdd(&cnt[c], 1);
}

__global__ void scan1_kernel(const int* __restrict__ cnt, int* incl, int* bsum, int n) {
    __shared__ int s[256];
    int i = blockIdx.x * 256 + threadIdx.x;
    int v = (i < n) ? cnt[i] : 0;
    s[threadIdx.x] = v;
    __syncthreads();
#pragma unroll
    for (int d = 1; d < 256; d <<= 1) {
        int t = (threadIdx.x >= d) ? s[threadIdx.x - d] : 0;
        __syncthreads();
        s[threadIdx.x] += t;
        __syncthreads();
    }
    if (i < n) incl[i] = s[threadIdx.x];
    if (threadIdx.x == 255) bsum[blockIdx.x] = s[255];
}

__global__ void scan2_kernel(int* bsum, int nb) {
    __shared__ int s[256];
    int v = (threadIdx.x < nb) ? bsum[threadIdx.x] : 0;
    s[threadIdx.x] = v;
    __syncthreads();
#pragma unroll
    for (int d = 1; d < 256; d <<= 1) {
        int t = (threadIdx.x >= d) ? s[threadIdx.x - d] : 0;
        __syncthreads();
        s[threadIdx.x] += t;
        __syncthreads();
    }
    if (threadIdx.x < nb) bsum[threadIdx.x] = s[threadIdx.x] - v;  // exclusive
}

__global__ void scan3_kernel(const int* __restrict__ incl, const int* __restrict__ bsum,
                             const int* __restrict__ cnt, int* off, int* cursor,
                             float* dinv, int n) {
    int i = blockIdx.x * blockDim.x + threadIdx.x;
    if (i >= n) return;
    int v = incl[i] + bsum[i >> 8];
    off[i + 1] = v;
    cursor[i]  = v - cnt[i];
    dinv[i]    = rsqrtf((float)cnt[i]);
    if (i == 0) off[0] = 0;
}

// fill: stores srcid AND srcdn = dinv[src] (kills the per-edge indirection in
// both gathers). Requires dinv ready (scan3 runs before).
__global__ void fill_kernel(int* cursor, int* srcid, float* srcdn,
                            const float* __restrict__ dinv,
                            const void* __restrict__ ei, int E, int n) {
    int e = blockIdx.x * blockDim.x + threadIdx.x;
    if (e >= E + n) return;
    int r, c;
    if (e < E) load_edge(ei, E, e, r, c);
    else       r = c = e - E;
    int p = atomicAdd(&cursor[c], 1);
    srcid[p] = r;
    srcdn[p] = dinv[r];
}

// ---------------------------------------------------------------------------
// Gather-aggregate (no atomics): one warp per destination node.
//   dst[c] = relu( bias + dinv[c] * sum_{r in N(c)} dinv[r] * src[r] )
// 4-way edge unroll -> 4 independent LDG.128 in flight per warp (MLP>=4).
// ---------------------------------------------------------------------------
__global__ void gather_kernel(const float* __restrict__ A, float* __restrict__ dst,
                              const int* __restrict__ srcid,
                              const float* __restrict__ srcdn,
                              const int* __restrict__ off,
                              const float* __restrict__ dinv,
                              const float* __restrict__ bias, int n) {
    int c    = (blockIdx.x * blockDim.x + threadIdx.x) >> 5;
    int lane = threadIdx.x & 31;
    if (c >= n) return;
    int s = off[c], e = off[c + 1];
    float dc = dinv[c];

    const float4* A4 = (const float4*)A;
    float ax0 = 0.f, ay0 = 0.f, az0 = 0.f, aw0 = 0.f;
    float ax1 = 0.f, ay1 = 0.f, az1 = 0.f, aw1 = 0.f;

    for (int base = s; base < e; base += 32) {
        int idx = base + lane;
        int r = 0; float dr = 0.f;
        if (idx < e) { r = srcid[idx]; dr = srcdn[idx]; }
        int m = min(32, e - base);
        int k = 0;
        for (; k + 4 <= m; k += 4) {
            int   r0 = __shfl_sync(0xffffffffu, r, k);
            int   r1 = __shfl_sync(0xffffffffu, r, k + 1);
            int   r2 = __shfl_sync(0xffffffffu, r, k + 2);
            int   r3 = __shfl_sync(0xffffffffu, r, k + 3);
            float d0 = __shfl_sync(0xffffffffu, dr, k);
            float d1 = __shfl_sync(0xffffffffu, dr, k + 1);
            float d2 = __shfl_sync(0xffffffffu, dr, k + 2);
            float d3 = __shfl_sync(0xffffffffu, dr, k + 3);
            float4 v0 = A4[(size_t)r0 * 32 + lane];
            float4 v1 = A4[(size_t)r1 * 32 + lane];
            float4 v2 = A4[(size_t)r2 * 32 + lane];
            float4 v3 = A4[(size_t)r3 * 32 + lane];
            ax0 += d0 * v0.x; ay0 += d0 * v0.y; az0 += d0 * v0.z; aw0 += d0 * v0.w;
            ax1 += d1 * v1.x; ay1 += d1 * v1.y; az1 += d1 * v1.z; aw1 += d1 * v1.w;
            ax0 += d2 * v2.x; ay0 += d2 * v2.y; az0 += d2 * v2.z; aw0 += d2 * v2.w;
            ax1 += d3 * v3.x; ay1 += d3 * v3.y; az1 += d3 * v3.z; aw1 += d3 * v3.w;
        }
        for (; k < m; ++k) {
            int   r0 = __shfl_sync(0xffffffffu, r, k);
            float d0 = __shfl_sync(0xffffffffu, dr, k);
            float4 v0 = A4[(size_t)r0 * 32 + lane];
            ax0 += d0 * v0.x; ay0 += d0 * v0.y; az0 += d0 * v0.z; aw0 += d0 * v0.w;
        }
    }
    float4 b = ((const float4*)bias)[lane];
    float4 o;
    o.x = fmaxf(b.x + dc * (ax0 + ax1), 0.f);
    o.y = fmaxf(b.y + dc * (ay0 + ay1), 0.f);
    o.z = fmaxf(b.z + dc * (az0 + az1), 0.f);
    o.w = fmaxf(b.w + dc * (aw0 + aw1), 0.f);
    ((float4*)dst)[(size_t)c * 32 + lane] = o;
}

// ---------------------------------------------------------------------------
// GEMM: C[n][COUT] = A[n][128] @ W[128][COUT] (+ bias). Inputs already relu'd
// where needed (relu fused into gather epilogue).
// ---------------------------------------------------------------------------
template <int COUT, bool BIAS>
__global__ void gemm_kernel(const float* __restrict__ A, const float* __restrict__ W,
                            const float* __restrict__ bias, float* __restrict__ C, int n) {
    extern __shared__ float smem[];
    float* WsT = smem;                 // [COUT][132]
    float* xs  = smem + COUT * 132;    // [4][128]
    int tid = threadIdx.x;             // one output column per thread

    for (int idx = tid; idx < 128 * COUT; idx += COUT) {
        int k = idx / COUT, c = idx % COUT;
        WsT[c * 132 + k] = W[idx];
    }
    float bv = 0.f;
    if (BIAS) bv = bias[tid];
    __syncthreads();

    int row0 = blockIdx.x * 64;
    const float4* wrow = (const float4*)(WsT + tid * 132);

    for (int rr = 0; rr < 64; rr += 4) {
        int rbase = row0 + rr;
        if (rbase >= n) return;

        for (int i = tid; i < 128; i += COUT) {
            int r = i >> 5, q = i & 31;
            int gr = rbase + r;
            float4 v = make_float4(0.f, 0.f, 0.f, 0.f);
            if (gr < n) v = ((const float4*)(A + (size_t)gr * 128))[q];
            ((float4*)xs)[i] = v;
        }
        __syncthreads();

        float a0 = 0.f, a1 = 0.f, a2 = 0.f, a3 = 0.f;
#pragma unroll
        for (int k4 = 0; k4 < 32; ++k4) {
            float4 w  = wrow[k4];
            float4 x0 = ((const float4*)(xs      ))[k4];
            float4 x1 = ((const float4*)(xs + 128))[k4];
            float4 x2 = ((const float4*)(xs + 256))[k4];
            float4 x3 = ((const float4*)(xs + 384))[k4];
            a0 += w.x * x0.x; a0 += w.y * x0.y; a0 += w.z * x0.z; a0 += w.w * x0.w;
            a1 += w.x * x1.x; a1 += w.y * x1.y; a1 += w.z * x1.z; a1 += w.w * x1.w;
            a2 += w.x * x2.x; a2 += w.y * x2.y; a2 += w.z * x2.z; a2 += w.w * x2.w;
            a3 += w.x * x3.x; a3 += w.y * x3.y; a3 += w.z * x3.z; a3 += w.w * x3.w;
        }
        if (BIAS) { a0 += bv; a1 += bv; a2 += bv; a3 += bv; }

        if (rbase + 0 < n) C[(size_t)(rbase + 0) * COUT + tid] = a0;
        if (rbase + 1 < n) C[(size_t)(rbase + 1) * COUT + tid] = a1;
        if (rbase + 2 < n) C[(size_t)(rbase + 2) * COUT + tid] = a2;
        if (rbase + 3 < n) C[(size_t)(rbase + 3) * COUT + tid] = a3;
        __syncthreads();
    }
}

// ---------------------------------------------------------------------------
// Launch. Inputs: x, edge_index, W1, b1, W2, b2, Wl, bl. Output: [n, 64] f32.
// ---------------------------------------------------------------------------
extern "C" void kernel_launch(void* const* d_in, const int* in_sizes, int n_in,
                              void* d_out, int out_size) {
    const float* x  = (const float*)d_in[0];
    const void*  ei = d_in[1];
    const float* W1 = (const float*)d_in[2];
    const float* b1 = (const float*)d_in[3];
    const float* W2 = (const float*)d_in[4];
    const float* b2 = (const float*)d_in[5];
    const float* Wl = (const float*)d_in[6];
    const float* bl = (const float*)d_in[7];
    float* out = (float*)d_out;

    int n = in_sizes[0] / 128;   // 50000
    int E = in_sizes[1] / 2;     // 640000

    float *dinv, *bufA, *bufB, *srcdn;
    int *cnt, *incl, *bsum, *off, *cursor, *srcid;
    cudaGetSymbolAddress((void**)&dinv,   g_dinv);
    cudaGetSymbolAddress((void**)&bufA,   g_bufA);
    cudaGetSymbolAddress((void**)&bufB,   g_bufB);
    cudaGetSymbolAddress((void**)&cnt,    g_cnt);
    cudaGetSymbolAddress((void**)&incl,   g_incl);
    cudaGetSymbolAddress((void**)&bsum,   g_bsum);
    cudaGetSymbolAddress((void**)&off,    g_off);
    cudaGetSymbolAddress((void**)&cursor, g_cursor);
    cudaGetSymbolAddress((void**)&srcid,  g_srcid);
    cudaGetSymbolAddress((void**)&srcdn,  g_srcdn);

    const size_t smem128 = 128 * 132 * sizeof(float) + 4 * 128 * sizeof(float);
    const size_t smem64  =  64 * 132 * sizeof(float) + 4 * 128 * sizeof(float);
    cudaFuncSetAttribute(gemm_kernel<128, false>,
                         cudaFuncAttributeMaxDynamicSharedMemorySize, (int)smem128);
    cudaFuncSetAttribute(gemm_kernel<64, true>,
                         cudaFuncAttributeMaxDynamicSharedMemorySize, (int)smem64);

    int nb256 = (n + 255) / 256;      // 196
    int EN = E + n;

    // CSR build (shared by both layers)
    detect_dtype_kernel<<<1, 32>>>((const int*)ei);
    cnt_init_kernel<<<nb256, 256>>>(cnt, n);
    cnt_count_kernel<<<(E + 255) / 256, 256>>>(cnt, ei, E);
    scan1_kernel<<<nb256, 256>>>(cnt, incl, bsum, n);
    scan2_kernel<<<1, 256>>>(bsum, nb256);
    scan3_kernel<<<nb256, 256>>>(incl, bsum, cnt, off, cursor, dinv, n);
    fill_kernel<<<(EN + 255) / 256, 256>>>(cursor, srcid, srcdn, dinv, ei, E, n);

    int gemm_blocks   = (n + 63) / 64;
    int gather_blocks = (n + 7) / 8;   // 8 warps/block, warp per node

    // Layer 1: h1 = relu( Agg(x @ W1) + b1 )   (relu fused into gather)
    gemm_kernel<128, false><<<gemm_blocks, 128, smem128>>>(x, W1, nullptr, bufA, n);
    gather_kernel<<<gather_blocks, 256>>>(bufA, bufB, srcid, srcdn, off, dinv, b1, n);

    // Layer 2: h2 = relu( Agg(h1 @ W2) + b2 )
    gemm_kernel<128, false><<<gemm_blocks, 128, smem128>>>(bufB, W2, nullptr, bufA, n);
    gather_kernel<<<gather_blocks, 256>>>(bufA, bufB, srcid, srcdn, off, dinv, b2, n);

    // Head: out = h2 @ Wl + bl
    gemm_kernel<64, true><<<gemm_blocks, 64, smem64>>>(bufB, Wl, bl, out, n);
}

// round 9
// speedup vs baseline: 1.0974x; 1.0974x over previous
#include <cuda_runtime.h>

#define NMAX 50000
#define EMAX 700000

// Scratch (allocation-free: __device__ globals)
__device__ float g_dinv[NMAX];
__device__ float g_bufA[(size_t)NMAX * 128];
__device__ float g_bufB[(size_t)NMAX * 128];
__device__ int   g_cnt[NMAX];
__device__ int   g_incl[NMAX];
__device__ int   g_bsum[256];
__device__ int   g_off[NMAX + 1];
__device__ int   g_cursor[NMAX];
__device__ int   g_srcid[EMAX];
__device__ float g_srcdn[EMAX];
__device__ int   g_is64;

// packed f32x2 FMA: acc = a*b + acc (element-wise on two packed floats)
#define FMA_F32X2(acc, a, b) \
    asm("fma.rn.f32x2 %0, %1, %2, %0;" : "+l"(acc) : "l"(a), "l"(b))

// ---------------------------------------------------------------------------
// edge_index dtype detection (int64 vs int32, see prior rounds)
// ---------------------------------------------------------------------------
__global__ void detect_dtype_kernel(const int* __restrict__ ei) {
    if (threadIdx.x == 0) {
        int nz = 0;
        for (int i = 1; i < 256; i += 2) nz |= (ei[i] != 0);
        g_is64 = nz ? 0 : 1;
    }
}

__device__ __forceinline__ void load_edge(const void* ei, int E, int e, int& r, int& c) {
    if (g_is64) {
        const long long* p = (const long long*)ei;
        r = (int)p[e];
        c = (int)p[(size_t)E + e];
    } else {
        const int* p = (const int*)ei;
        r = p[e];
        c = p[E + e];
    }
}

// ---------------------------------------------------------------------------
// CSR build: counting sort of edges by destination (col), self-loops included.
// ---------------------------------------------------------------------------
__global__ void cnt_init_kernel(int* cnt, int n) {
    int i = blockIdx.x * blockDim.x + threadIdx.x;
    if (i < n) cnt[i] = 1;  // self-loop
}

__global__ void cnt_count_kernel(int* cnt, const void* __restrict__ ei, int E) {
    int e = blockIdx.x * blockDim.x + threadIdx.x;
    if (e >= E) return;
    int c;
    if (g_is64) c = (int)((const long long*)ei)[(size_t)E + e];
    else        c = ((const int*)ei)[E + e];
    atomicAdd(&cnt[c], 1);
}

__global__ void scan1_kernel(const int* __restrict__ cnt, int* incl, int* bsum, int n) {
    __shared__ int s[256];
    int i = blockIdx.x * 256 + threadIdx.x;
    int v = (i < n) ? cnt[i] : 0;
    s[threadIdx.x] = v;
    __syncthreads();
#pragma unroll
    for (int d = 1; d < 256; d <<= 1) {
        int t = (threadIdx.x >= d) ? s[threadIdx.x - d] : 0;
        __syncthreads();
        s[threadIdx.x] += t;
        __syncthreads();
    }
    if (i < n) incl[i] = s[threadIdx.x];
    if (threadIdx.x == 255) bsum[blockIdx.x] = s[255];
}

__global__ void scan2_kernel(int* bsum, int nb) {
    __shared__ int s[256];
    int v = (threadIdx.x < nb) ? bsum[threadIdx.x] : 0;
    s[threadIdx.x] = v;
    __syncthreads();
#pragma unroll
    for (int d = 1; d < 256; d <<= 1) {
        int t = (threadIdx.x >= d) ? s[threadIdx.x - d] : 0;
        __syncthreads();
        s[threadIdx.x] += t;
        __syncthreads();
    }
    if (threadIdx.x < nb) bsum[threadIdx.x] = s[threadIdx.x] - v;  // exclusive
}

__global__ void scan3_kernel(const int* __restrict__ incl, const int* __restrict__ bsum,
                             const int* __restrict__ cnt, int* off, int* cursor,
                             float* dinv, int n) {
    int i = blockIdx.x * blockDim.x + threadIdx.x;
    if (i >= n) return;
    int v = incl[i] + bsum[i >> 8];
    off[i + 1] = v;
    cursor[i]  = v - cnt[i];
    dinv[i]    = rsqrtf((float)cnt[i]);
    if (i == 0) off[0] = 0;
}

__global__ void fill_kernel(int* cursor, int* srcid, float* srcdn,
                            const float* __restrict__ dinv,
                            const void* __restrict__ ei, int E, int n) {
    int e = blockIdx.x * blockDim.x + threadIdx.x;
    if (e >= E + n) return;
    int r, c;
    if (e < E) load_edge(ei, E, e, r, c);
    else       r = c = e - E;
    int p = atomicAdd(&cursor[c], 1);
    srcid[p] = r;
    srcdn[p] = dinv[r];
}

// ---------------------------------------------------------------------------
// Gather-aggregate (no atomics): one warp per destination node.
//   dst[c] = relu( bias + dinv[c] * sum_{r in N(c)} dinv[r] * src[r] )
// ---------------------------------------------------------------------------
__global__ void gather_kernel(const float* __restrict__ A, float* __restrict__ dst,
                              const int* __restrict__ srcid,
                              const float* __restrict__ srcdn,
                              const int* __restrict__ off,
                              const float* __restrict__ dinv,
                              const float* __restrict__ bias, int n) {
    int c    = (blockIdx.x * blockDim.x + threadIdx.x) >> 5;
    int lane = threadIdx.x & 31;
    if (c >= n) return;
    int s = off[c], e = off[c + 1];
    float dc = dinv[c];

    const float4* A4 = (const float4*)A;
    float ax0 = 0.f, ay0 = 0.f, az0 = 0.f, aw0 = 0.f;
    float ax1 = 0.f, ay1 = 0.f, az1 = 0.f, aw1 = 0.f;

    for (int base = s; base < e; base += 32) {
        int idx = base + lane;
        int r = 0; float dr = 0.f;
        if (idx < e) { r = srcid[idx]; dr = srcdn[idx]; }
        int m = min(32, e - base);
        int k = 0;
        for (; k + 4 <= m; k += 4) {
            int   r0 = __shfl_sync(0xffffffffu, r, k);
            int   r1 = __shfl_sync(0xffffffffu, r, k + 1);
            int   r2 = __shfl_sync(0xffffffffu, r, k + 2);
            int   r3 = __shfl_sync(0xffffffffu, r, k + 3);
            float d0 = __shfl_sync(0xffffffffu, dr, k);
            float d1 = __shfl_sync(0xffffffffu, dr, k + 1);
            float d2 = __shfl_sync(0xffffffffu, dr, k + 2);
            float d3 = __shfl_sync(0xffffffffu, dr, k + 3);
            float4 v0 = A4[(size_t)r0 * 32 + lane];
            float4 v1 = A4[(size_t)r1 * 32 + lane];
            float4 v2 = A4[(size_t)r2 * 32 + lane];
            float4 v3 = A4[(size_t)r3 * 32 + lane];
            ax0 += d0 * v0.x; ay0 += d0 * v0.y; az0 += d0 * v0.z; aw0 += d0 * v0.w;
            ax1 += d1 * v1.x; ay1 += d1 * v1.y; az1 += d1 * v1.z; aw1 += d1 * v1.w;
            ax0 += d2 * v2.x; ay0 += d2 * v2.y; az0 += d2 * v2.z; aw0 += d2 * v2.w;
            ax1 += d3 * v3.x; ay1 += d3 * v3.y; az1 += d3 * v3.z; aw1 += d3 * v3.w;
        }
        for (; k < m; ++k) {
            int   r0 = __shfl_sync(0xffffffffu, r, k);
            float d0 = __shfl_sync(0xffffffffu, dr, k);
            float4 v0 = A4[(size_t)r0 * 32 + lane];
            ax0 += d0 * v0.x; ay0 += d0 * v0.y; az0 += d0 * v0.z; aw0 += d0 * v0.w;
        }
    }
    float4 b = ((const float4*)bias)[lane];
    float4 o;
    o.x = fmaxf(b.x + dc * (ax0 + ax1), 0.f);
    o.y = fmaxf(b.y + dc * (ay0 + ay1), 0.f);
    o.z = fmaxf(b.z + dc * (az0 + az1), 0.f);
    o.w = fmaxf(b.w + dc * (aw0 + aw1), 0.f);
    ((float4*)dst)[(size_t)c * 32 + lane] = o;
}

// ---------------------------------------------------------------------------
// GEMM: C[n][COUT] = A[n][128] @ W[128][COUT] (+ bias), fp32 via fma.rn.f32x2.
// Thread = output column. k4-outer / 16-rows-inner: the per-thread-distinct
// w load (4 smem wavefronts) is amortized over 16 broadcast x loads; packed
// f32x2 accumulators (even/odd k partials) halve FFMA instruction count.
// ---------------------------------------------------------------------------
template <int COUT, bool BIAS>
__global__ void gemm_kernel(const float* __restrict__ A, const float* __restrict__ W,
                            const float* __restrict__ bias, float* __restrict__ C, int n) {
    extern __shared__ float smem[];
    float* WsT = smem;                 // [COUT][132] transposed, pad 132
    float* xs  = smem + COUT * 132;    // [16][128]
    int tid = threadIdx.x;             // one output column per thread

    for (int idx = tid; idx < 128 * COUT; idx += COUT) {
        int k = idx / COUT, c = idx % COUT;
        WsT[c * 132 + k] = W[idx];
    }
    float bv = 0.f;
    if (BIAS) bv = bias[tid];
    __syncthreads();

    int row0 = blockIdx.x * 64;
    const ulonglong2* wrow = (const ulonglong2*)(WsT + tid * 132);  // 528B stride, 16B aligned

    for (int rr = 0; rr < 64; rr += 16) {
        int rbase = row0 + rr;
        if (rbase >= n) return;  // block-uniform (rbase identical across block)

        // stage 16 input rows
        for (int i = tid; i < 16 * 32; i += COUT) {
            int r = i >> 5, q = i & 31;
            int gr = rbase + r;
            float4 v = make_float4(0.f, 0.f, 0.f, 0.f);
            if (gr < n) v = ((const float4*)(A + (size_t)gr * 128))[q];
            ((float4*)xs)[i] = v;
        }
        __syncthreads();

        unsigned long long acc[16];
#pragma unroll
        for (int r = 0; r < 16; ++r) acc[r] = 0ull;  // {0.f, 0.f}

#pragma unroll 4
        for (int k4 = 0; k4 < 32; ++k4) {
            ulonglong2 w2 = wrow[k4];  // {w[4k],w[4k+1]} , {w[4k+2],w[4k+3]}
#pragma unroll
            for (int r = 0; r < 16; ++r) {
                ulonglong2 x2 = ((const ulonglong2*)(xs + r * 128))[k4];  // broadcast
                FMA_F32X2(acc[r], w2.x, x2.x);
                FMA_F32X2(acc[r], w2.y, x2.y);
            }
        }
        __syncthreads();

#pragma unroll
        for (int r = 0; r < 16; ++r) {
            int gr = rbase + r;
            if (gr < n) {
                float lo = __uint_as_float((unsigned)(acc[r] & 0xffffffffull));
                float hi = __uint_as_float((unsigned)(acc[r] >> 32));
                C[(size_t)gr * COUT + tid] = lo + hi + bv;
            }
        }
    }
}

// ---------------------------------------------------------------------------
// Launch. Inputs: x, edge_index, W1, b1, W2, b2, Wl, bl. Output: [n, 64] f32.
// ---------------------------------------------------------------------------
extern "C" void kernel_launch(void* const* d_in, const int* in_sizes, int n_in,
                              void* d_out, int out_size) {
    const float* x  = (const float*)d_in[0];
    const void*  ei = d_in[1];
    const float* W1 = (const float*)d_in[2];
    const float* b1 = (const float*)d_in[3];
    const float* W2 = (const float*)d_in[4];
    const float* b2 = (const float*)d_in[5];
    const float* Wl = (const float*)d_in[6];
    const float* bl = (const float*)d_in[7];
    float* out = (float*)d_out;

    int n = in_sizes[0] / 128;   // 50000
    int E = in_sizes[1] / 2;     // 640000

    float *dinv, *bufA, *bufB, *srcdn;
    int *cnt, *incl, *bsum, *off, *cursor, *srcid;
    cudaGetSymbolAddress((void**)&dinv,   g_dinv);
    cudaGetSymbolAddress((void**)&bufA,   g_bufA);
    cudaGetSymbolAddress((void**)&bufB,   g_bufB);
    cudaGetSymbolAddress((void**)&cnt,    g_cnt);
    cudaGetSymbolAddress((void**)&incl,   g_incl);
    cudaGetSymbolAddress((void**)&bsum,   g_bsum);
    cudaGetSymbolAddress((void**)&off,    g_off);
    cudaGetSymbolAddress((void**)&cursor, g_cursor);
    cudaGetSymbolAddress((void**)&srcid,  g_srcid);
    cudaGetSymbolAddress((void**)&srcdn,  g_srcdn);

    const size_t smem128 = 128 * 132 * sizeof(float) + 16 * 128 * sizeof(float); // 75776
    const size_t smem64  =  64 * 132 * sizeof(float) + 16 * 128 * sizeof(float); // 41984
    cudaFuncSetAttribute(gemm_kernel<128, false>,
                         cudaFuncAttributeMaxDynamicSharedMemorySize, (int)smem128);
    cudaFuncSetAttribute(gemm_kernel<64, true>,
                         cudaFuncAttributeMaxDynamicSharedMemorySize, (int)smem64);

    int nb256 = (n + 255) / 256;      // 196
    int EN = E + n;
    int gemm_blocks   = (n + 63) / 64;
    int gather_blocks = (n + 7) / 8;

    // CSR build interleaved; gemm1 (independent of CSR) placed 4th so the
    // ncu capture window lands on it.
    detect_dtype_kernel<<<1, 32>>>((const int*)ei);
    cnt_init_kernel<<<nb256, 256>>>(cnt, n);
    cnt_count_kernel<<<(E + 255) / 256, 256>>>(cnt, ei, E);
    gemm_kernel<128, false><<<gemm_blocks, 128, smem128>>>(x, W1, nullptr, bufA, n);
    scan1_kernel<<<nb256, 256>>>(cnt, incl, bsum, n);
    scan2_kernel<<<1, 256>>>(bsum, nb256);
    scan3_kernel<<<nb256, 256>>>(incl, bsum, cnt, off, cursor, dinv, n);
    fill_kernel<<<(EN + 255) / 256, 256>>>(cursor, srcid, srcdn, dinv, ei, E, n);

    // Layer 1 aggregate: h1 = relu( Agg(x @ W1) + b1 )
    gather_kernel<<<gather_blocks, 256>>>(bufA, bufB, srcid, srcdn, off, dinv, b1, n);

    // Layer 2: h2 = relu( Agg(h1 @ W2) + b2 )
    gemm_kernel<128, false><<<gemm_blocks, 128, smem128>>>(bufB, W2, nullptr, bufA, n);
    gather_kernel<<<gather_blocks, 256>>>(bufA, bufB, srcid, srcdn, off, dinv, b2, n);

    // Head: out = h2 @ Wl + bl
    gemm_kernel<64, true><<<gemm_blocks, 64, smem64>>>(bufB, Wl, bl, out, n);
}

// round 10
// speedup vs baseline: 1.6247x; 1.4805x over previous
#include <cuda_runtime.h>

#define NMAX 50000
#define EMAX 700000

// Scratch (allocation-free: __device__ globals)
__device__ float g_dinv[NMAX];
__device__ float g_bufA[(size_t)NMAX * 128];
__device__ float g_bufB[(size_t)NMAX * 128];
__device__ int   g_cnt[NMAX];
__device__ int   g_incl[NMAX];
__device__ int   g_bsum[256];
__device__ int   g_off[NMAX + 1];
__device__ int   g_cursor[NMAX];
__device__ int   g_srcid[EMAX];
__device__ float g_srcdn[EMAX];
__device__ int   g_is64;

// packed f32x2 FMA: acc = a*b + acc (element-wise on two packed floats)
#define FMA_F32X2(acc, a, b) \
    asm("fma.rn.f32x2 %0, %1, %2, %0;" : "+l"(acc) : "l"(a), "l"(b))
#define PACK2(dst, lo, hi) \
    asm("mov.b64 %0, {%1, %2};" : "=l"(dst) : "f"(lo), "f"(hi))
#define UNPACK2(lo, hi, src) \
    asm("mov.b64 {%0, %1}, %2;" : "=f"(lo), "=f"(hi) : "l"(src))

// ---------------------------------------------------------------------------
// edge_index dtype detection (int64 vs int32, see prior rounds)
// ---------------------------------------------------------------------------
__global__ void detect_dtype_kernel(const int* __restrict__ ei) {
    if (threadIdx.x == 0) {
        int nz = 0;
        for (int i = 1; i < 256; i += 2) nz |= (ei[i] != 0);
        g_is64 = nz ? 0 : 1;
    }
}

__device__ __forceinline__ void load_edge(const void* ei, int E, int e, int& r, int& c) {
    if (g_is64) {
        const long long* p = (const long long*)ei;
        r = (int)p[e];
        c = (int)p[(size_t)E + e];
    } else {
        const int* p = (const int*)ei;
        r = p[e];
        c = p[E + e];
    }
}

// ---------------------------------------------------------------------------
// CSR build: counting sort of edges by destination (col), self-loops included.
// ---------------------------------------------------------------------------
__global__ void cnt_init_kernel(int* cnt, int n) {
    int i = blockIdx.x * blockDim.x + threadIdx.x;
    if (i < n) cnt[i] = 1;  // self-loop
}

__global__ void cnt_count_kernel(int* cnt, const void* __restrict__ ei, int E) {
    int e = blockIdx.x * blockDim.x + threadIdx.x;
    if (e >= E) return;
    int c;
    if (g_is64) c = (int)((const long long*)ei)[(size_t)E + e];
    else        c = ((const int*)ei)[E + e];
    atomicAdd(&cnt[c], 1);
}

__global__ void scan1_kernel(const int* __restrict__ cnt, int* incl, int* bsum, int n) {
    __shared__ int s[256];
    int i = blockIdx.x * 256 + threadIdx.x;
    int v = (i < n) ? cnt[i] : 0;
    s[threadIdx.x] = v;
    __syncthreads();
#pragma unroll
    for (int d = 1; d < 256; d <<= 1) {
        int t = (threadIdx.x >= d) ? s[threadIdx.x - d] : 0;
        __syncthreads();
        s[threadIdx.x] += t;
        __syncthreads();
    }
    if (i < n) incl[i] = s[threadIdx.x];
    if (threadIdx.x == 255) bsum[blockIdx.x] = s[255];
}

__global__ void scan2_kernel(int* bsum, int nb) {
    __shared__ int s[256];
    int v = (threadIdx.x < nb) ? bsum[threadIdx.x] : 0;
    s[threadIdx.x] = v;
    __syncthreads();
#pragma unroll
    for (int d = 1; d < 256; d <<= 1) {
        int t = (threadIdx.x >= d) ? s[threadIdx.x - d] : 0;
        __syncthreads();
        s[threadIdx.x] += t;
        __syncthreads();
    }
    if (threadIdx.x < nb) bsum[threadIdx.x] = s[threadIdx.x] - v;  // exclusive
}

__global__ void scan3_kernel(const int* __restrict__ incl, const int* __restrict__ bsum,
                             const int* __restrict__ cnt, int* off, int* cursor,
                             float* dinv, int n) {
    int i = blockIdx.x * blockDim.x + threadIdx.x;
    if (i >= n) return;
    int v = incl[i] + bsum[i >> 8];
    off[i + 1] = v;
    cursor[i]  = v - cnt[i];
    dinv[i]    = rsqrtf((float)cnt[i]);
    if (i == 0) off[0] = 0;
}

__global__ void fill_kernel(int* cursor, int* srcid, float* srcdn,
                            const float* __restrict__ dinv,
                            const void* __restrict__ ei, int E, int n) {
    int e = blockIdx.x * blockDim.x + threadIdx.x;
    if (e >= E + n) return;
    int r, c;
    if (e < E) load_edge(ei, E, e, r, c);
    else       r = c = e - E;
    int p = atomicAdd(&cursor[c], 1);
    srcid[p] = r;
    srcdn[p] = dinv[r];
}

// ---------------------------------------------------------------------------
// Gather-aggregate (no atomics): one warp per destination node.
//   dst[c] = relu( bias + dinv[c] * sum_{r in N(c)} dinv[r] * src[r] )
// ---------------------------------------------------------------------------
__global__ void gather_kernel(const float* __restrict__ A, float* __restrict__ dst,
                              const int* __restrict__ srcid,
                              const float* __restrict__ srcdn,
                              const int* __restrict__ off,
                              const float* __restrict__ dinv,
                              const float* __restrict__ bias, int n) {
    int c    = (blockIdx.x * blockDim.x + threadIdx.x) >> 5;
    int lane = threadIdx.x & 31;
    if (c >= n) return;
    int s = off[c], e = off[c + 1];
    float dc = dinv[c];

    const float4* A4 = (const float4*)A;
    float ax0 = 0.f, ay0 = 0.f, az0 = 0.f, aw0 = 0.f;
    float ax1 = 0.f, ay1 = 0.f, az1 = 0.f, aw1 = 0.f;

    for (int base = s; base < e; base += 32) {
        int idx = base + lane;
        int r = 0; float dr = 0.f;
        if (idx < e) { r = srcid[idx]; dr = srcdn[idx]; }
        int m = min(32, e - base);
        int k = 0;
        for (; k + 4 <= m; k += 4) {
            int   r0 = __shfl_sync(0xffffffffu, r, k);
            int   r1 = __shfl_sync(0xffffffffu, r, k + 1);
            int   r2 = __shfl_sync(0xffffffffu, r, k + 2);
            int   r3 = __shfl_sync(0xffffffffu, r, k + 3);
            float d0 = __shfl_sync(0xffffffffu, dr, k);
            float d1 = __shfl_sync(0xffffffffu, dr, k + 1);
            float d2 = __shfl_sync(0xffffffffu, dr, k + 2);
            float d3 = __shfl_sync(0xffffffffu, dr, k + 3);
            float4 v0 = A4[(size_t)r0 * 32 + lane];
            float4 v1 = A4[(size_t)r1 * 32 + lane];
            float4 v2 = A4[(size_t)r2 * 32 + lane];
            float4 v3 = A4[(size_t)r3 * 32 + lane];
            ax0 += d0 * v0.x; ay0 += d0 * v0.y; az0 += d0 * v0.z; aw0 += d0 * v0.w;
            ax1 += d1 * v1.x; ay1 += d1 * v1.y; az1 += d1 * v1.z; aw1 += d1 * v1.w;
            ax0 += d2 * v2.x; ay0 += d2 * v2.y; az0 += d2 * v2.z; aw0 += d2 * v2.w;
            ax1 += d3 * v3.x; ay1 += d3 * v3.y; az1 += d3 * v3.z; aw1 += d3 * v3.w;
        }
        for (; k < m; ++k) {
            int   r0 = __shfl_sync(0xffffffffu, r, k);
            float d0 = __shfl_sync(0xffffffffu, dr, k);
            float4 v0 = A4[(size_t)r0 * 32 + lane];
            ax0 += d0 * v0.x; ay0 += d0 * v0.y; az0 += d0 * v0.z; aw0 += d0 * v0.w;
        }
    }
    float4 b = ((const float4*)bias)[lane];
    float4 o;
    o.x = fmaxf(b.x + dc * (ax0 + ax1), 0.f);
    o.y = fmaxf(b.y + dc * (ay0 + ay1), 0.f);
    o.z = fmaxf(b.z + dc * (az0 + az1), 0.f);
    o.w = fmaxf(b.w + dc * (aw0 + aw1), 0.f);
    ((float4*)dst)[(size_t)c * 32 + lane] = o;
}

// ---------------------------------------------------------------------------
// Register-tiled GEMM: C[n][COUT] = A[n][128] @ W[128][COUT] (+ bias).
// Block tile 128 rows x 64 cols (blockIdx.y = col block), 256 threads,
// 8x4 micro-tile/thread, K chunked by 32. Operands staged in smem pre-packed
// as f32x2 k-pairs -> inner loop is 6 LDS.128 + 32 FFMA2 per k2 (84% fma).
// Accumulators hold even/odd-k partials, summed in the epilogue.
// ---------------------------------------------------------------------------
template <int COUT, bool BIAS>
__global__ __launch_bounds__(256, 2)
void gemm_kernel(const float* __restrict__ A, const float* __restrict__ W,
                 const float* __restrict__ bias, float* __restrict__ C, int n) {
    __shared__ unsigned long long As2[16][130];  // [k2][row] {A[row][2k2],A[row][2k2+1]}, pad->16B align
    __shared__ unsigned long long Ws2[16][64];   // [k2][col] {W[2k2][col],W[2k2+1][col]}

    int tid = threadIdx.x;
    int tc  = tid & 15;   // col group: 4 cols
    int tr  = tid >> 4;   // row group: 8 rows
    int r0  = blockIdx.x * 128;
    int c0  = blockIdx.y * 64;

    unsigned long long acc[8][4];
#pragma unroll
    for (int r = 0; r < 8; ++r)
#pragma unroll
        for (int c = 0; c < 4; ++c) acc[r][c] = 0ull;

    const float4* A4 = (const float4*)A;

    for (int kc = 0; kc < 4; ++kc) {
        // stage A chunk (transpose+pack): coalesced f4 reads, 4 rows x 8 q per warp
        {
            int q   = tid & 7;    // float4 index within chunk
            int row = tid >> 3;   // 0..31
#pragma unroll
            for (int i = 0; i < 4; ++i) {
                int rr = row + i * 32;
                int gr = r0 + rr;
                float4 v = make_float4(0.f, 0.f, 0.f, 0.f);
                if (gr < n) v = A4[(size_t)gr * 32 + kc * 8 + q];
                unsigned long long p0, p1;
                PACK2(p0, v.x, v.y);
                PACK2(p1, v.z, v.w);
                As2[2 * q    ][rr] = p0;
                As2[2 * q + 1][rr] = p1;
            }
        }
        // stage W chunk (pack k-pairs): one (k2, 4-col group) task per thread
        {
            int cg = tid & 15;
            int k2 = tid >> 4;
            int gk = kc * 32 + 2 * k2;
            float4 wa = ((const float4*)(W + (size_t)gk * COUT))[(c0 >> 2) + cg];
            float4 wb = ((const float4*)(W + (size_t)(gk + 1) * COUT))[(c0 >> 2) + cg];
            unsigned long long p;
            PACK2(p, wa.x, wb.x); Ws2[k2][cg * 4 + 0] = p;
            PACK2(p, wa.y, wb.y); Ws2[k2][cg * 4 + 1] = p;
            PACK2(p, wa.z, wb.z); Ws2[k2][cg * 4 + 2] = p;
            PACK2(p, wa.w, wb.w); Ws2[k2][cg * 4 + 3] = p;
        }
        __syncthreads();

#pragma unroll
        for (int k2 = 0; k2 < 16; ++k2) {
            unsigned long long a[8], w[4];
            const ulonglong2* ap = (const ulonglong2*)&As2[k2][tr * 8];  // broadcast loads
            ulonglong2 t;
            t = ap[0]; a[0] = t.x; a[1] = t.y;
            t = ap[1]; a[2] = t.x; a[3] = t.y;
            t = ap[2]; a[4] = t.x; a[5] = t.y;
            t = ap[3]; a[6] = t.x; a[7] = t.y;
            const ulonglong2* wp = (const ulonglong2*)&Ws2[k2][tc * 4];
            t = wp[0]; w[0] = t.x; w[1] = t.y;
            t = wp[1]; w[2] = t.x; w[3] = t.y;
#pragma unroll
            for (int r = 0; r < 8; ++r)
#pragma unroll
                for (int c = 0; c < 4; ++c)
                    FMA_F32X2(acc[r][c], a[r], w[c]);
        }
        __syncthreads();
    }

    // epilogue: reduce k-even/odd partials, add bias, vector store
#pragma unroll
    for (int r = 0; r < 8; ++r) {
        int gr = r0 + tr * 8 + r;
        if (gr >= n) break;  // rows monotone in r
        float v[4];
#pragma unroll
        for (int c = 0; c < 4; ++c) {
            float lo, hi;
            UNPACK2(lo, hi, acc[r][c]);
            v[c] = lo + hi;
        }
        if (BIAS) {
            float4 b = ((const float4*)bias)[(c0 >> 2) + tc];
            v[0] += b.x; v[1] += b.y; v[2] += b.z; v[3] += b.w;
        }
        ((float4*)(C + (size_t)gr * COUT))[(c0 >> 2) + tc] =
            make_float4(v[0], v[1], v[2], v[3]);
    }
}

// ---------------------------------------------------------------------------
// Launch. Inputs: x, edge_index, W1, b1, W2, b2, Wl, bl. Output: [n, 64] f32.
// ---------------------------------------------------------------------------
extern "C" void kernel_launch(void* const* d_in, const int* in_sizes, int n_in,
                              void* d_out, int out_size) {
    const float* x  = (const float*)d_in[0];
    const void*  ei = d_in[1];
    const float* W1 = (const float*)d_in[2];
    const float* b1 = (const float*)d_in[3];
    const float* W2 = (const float*)d_in[4];
    const float* b2 = (const float*)d_in[5];
    const float* Wl = (const float*)d_in[6];
    const float* bl = (const float*)d_in[7];
    float* out = (float*)d_out;

    int n = in_sizes[0] / 128;   // 50000
    int E = in_sizes[1] / 2;     // 640000

    float *dinv, *bufA, *bufB, *srcdn;
    int *cnt, *incl, *bsum, *off, *cursor, *srcid;
    cudaGetSymbolAddress((void**)&dinv,   g_dinv);
    cudaGetSymbolAddress((void**)&bufA,   g_bufA);
    cudaGetSymbolAddress((void**)&bufB,   g_bufB);
    cudaGetSymbolAddress((void**)&cnt,    g_cnt);
    cudaGetSymbolAddress((void**)&incl,   g_incl);
    cudaGetSymbolAddress((void**)&bsum,   g_bsum);
    cudaGetSymbolAddress((void**)&off,    g_off);
    cudaGetSymbolAddress((void**)&cursor, g_cursor);
    cudaGetSymbolAddress((void**)&srcid,  g_srcid);
    cudaGetSymbolAddress((void**)&srcdn,  g_srcdn);

    int nb256 = (n + 255) / 256;      // 196
    int EN = E + n;
    int rowb = (n + 127) / 128;       // 391
    dim3 grid128(rowb, 2);            // COUT=128: 2 col blocks of 64
    dim3 grid64(rowb, 1);
    int gather_blocks = (n + 7) / 8;

    // CSR build interleaved; gemm1 (independent of CSR) placed 4th so the
    // ncu capture window lands on it.
    detect_dtype_kernel<<<1, 32>>>((const int*)ei);
    cnt_init_kernel<<<nb256, 256>>>(cnt, n);
    cnt_count_kernel<<<(E + 255) / 256, 256>>>(cnt, ei, E);
    gemm_kernel<128, false><<<grid128, 256>>>(x, W1, nullptr, bufA, n);
    scan1_kernel<<<nb256, 256>>>(cnt, incl, bsum, n);
    scan2_kernel<<<1, 256>>>(bsum, nb256);
    scan3_kernel<<<nb256, 256>>>(incl, bsum, cnt, off, cursor, dinv, n);
    fill_kernel<<<(EN + 255) / 256, 256>>>(cursor, srcid, srcdn, dinv, ei, E, n);

    // Layer 1 aggregate: h1 = relu( Agg(x @ W1) + b1 )
    gather_kernel<<<gather_blocks, 256>>>(bufA, bufB, srcid, srcdn, off, dinv, b1, n);

    // Layer 2: h2 = relu( Agg(h1 @ W2) + b2 )
    gemm_kernel<128, false><<<grid128, 256>>>(bufB, W2, nullptr, bufA, n);
    gather_kernel<<<gather_blocks, 256>>>(bufA, bufB, srcid, srcdn, off, dinv, b2, n);

    // Head: out = h2 @ Wl + bl
    gemm_kernel<64, true><<<grid64, 256>>>(bufB, Wl, bl, out, n);
}

// round 11
// speedup vs baseline: 1.6402x; 1.0096x over previous
#include <cuda_runtime.h>

#define NMAX 50000
#define EMAX 700000

// Scratch (allocation-free: __device__ globals)
__device__ float g_dinv[NMAX];
__device__ float g_bufA[(size_t)NMAX * 128];
__device__ float g_bufB[(size_t)NMAX * 128];
__device__ int   g_cnt[NMAX];
__device__ int   g_incl[NMAX];
__device__ int   g_bsum[256];
__device__ int   g_off[NMAX + 1];
__device__ int   g_cursor[NMAX];
__device__ int   g_srcid[EMAX];
__device__ float g_srcdn[EMAX];
__device__ int   g_is64;

// packed f32x2 FMA: acc = a*b + acc (element-wise on two packed floats)
#define FMA_F32X2(acc, a, b) \
    asm("fma.rn.f32x2 %0, %1, %2, %0;" : "+l"(acc) : "l"(a), "l"(b))
#define PACK2(dst, lo, hi) \
    asm("mov.b64 %0, {%1, %2};" : "=l"(dst) : "f"(lo), "f"(hi))
#define UNPACK2(lo, hi, src) \
    asm("mov.b64 {%0, %1}, %2;" : "=f"(lo), "=f"(hi) : "l"(src))

// ---------------------------------------------------------------------------
// edge_index dtype detection (int64 vs int32, see prior rounds)
// ---------------------------------------------------------------------------
__global__ void detect_dtype_kernel(const int* __restrict__ ei) {
    if (threadIdx.x == 0) {
        int nz = 0;
        for (int i = 1; i < 256; i += 2) nz |= (ei[i] != 0);
        g_is64 = nz ? 0 : 1;
    }
}

__device__ __forceinline__ void load_edge(const void* ei, int E, int e, int& r, int& c) {
    if (g_is64) {
        const long long* p = (const long long*)ei;
        r = (int)p[e];
        c = (int)p[(size_t)E + e];
    } else {
        const int* p = (const int*)ei;
        r = p[e];
        c = p[E + e];
    }
}

// ---------------------------------------------------------------------------
// CSR build: counting sort of edges by destination (col), self-loops included.
// ---------------------------------------------------------------------------
__global__ void cnt_init_kernel(int* cnt, int n) {
    int i = blockIdx.x * blockDim.x + threadIdx.x;
    if (i < n) cnt[i] = 1;  // self-loop
}

__global__ void cnt_count_kernel(int* cnt, const void* __restrict__ ei, int E) {
    int e = blockIdx.x * blockDim.x + threadIdx.x;
    if (e >= E) return;
    int c;
    if (g_is64) c = (int)((const long long*)ei)[(size_t)E + e];
    else        c = ((const int*)ei)[E + e];
    atomicAdd(&cnt[c], 1);
}

__global__ void scan1_kernel(const int* __restrict__ cnt, int* incl, int* bsum, int n) {
    __shared__ int s[256];
    int i = blockIdx.x * 256 + threadIdx.x;
    int v = (i < n) ? cnt[i] : 0;
    s[threadIdx.x] = v;
    __syncthreads();
#pragma unroll
    for (int d = 1; d < 256; d <<= 1) {
        int t = (threadIdx.x >= d) ? s[threadIdx.x - d] : 0;
        __syncthreads();
        s[threadIdx.x] += t;
        __syncthreads();
    }
    if (i < n) incl[i] = s[threadIdx.x];
    if (threadIdx.x == 255) bsum[blockIdx.x] = s[255];
}

__global__ void scan2_kernel(int* bsum, int nb) {
    __shared__ int s[256];
    int v = (threadIdx.x < nb) ? bsum[threadIdx.x] : 0;
    s[threadIdx.x] = v;
    __syncthreads();
#pragma unroll
    for (int d = 1; d < 256; d <<= 1) {
        int t = (threadIdx.x >= d) ? s[threadIdx.x - d] : 0;
        __syncthreads();
        s[threadIdx.x] += t;
        __syncthreads();
    }
    if (threadIdx.x < nb) bsum[threadIdx.x] = s[threadIdx.x] - v;  // exclusive
}

__global__ void scan3_kernel(const int* __restrict__ incl, const int* __restrict__ bsum,
                             const int* __restrict__ cnt, int* off, int* cursor,
                             float* dinv, int n) {
    int i = blockIdx.x * blockDim.x + threadIdx.x;
    if (i >= n) return;
    int v = incl[i] + bsum[i >> 8];
    off[i + 1] = v;
    cursor[i]  = v - cnt[i];
    dinv[i]    = rsqrtf((float)cnt[i]);
    if (i == 0) off[0] = 0;
}

__global__ void fill_kernel(int* cursor, int* srcid, float* srcdn,
                            const float* __restrict__ dinv,
                            const void* __restrict__ ei, int E, int n) {
    int e = blockIdx.x * blockDim.x + threadIdx.x;
    if (e >= E + n) return;
    int r, c;
    if (e < E) load_edge(ei, E, e, r, c);
    else       r = c = e - E;
    int p = atomicAdd(&cursor[c], 1);
    srcid[p] = r;
    srcdn[p] = dinv[r];
}

// ---------------------------------------------------------------------------
// Gather-aggregate (no atomics): one warp per destination node.
//   dst[c] = relu( bias + dinv[c] * sum_{r in N(c)} dinv[r] * src[r] )
// ---------------------------------------------------------------------------
__global__ void gather_kernel(const float* __restrict__ A, float* __restrict__ dst,
                              const int* __restrict__ srcid,
                              const float* __restrict__ srcdn,
                              const int* __restrict__ off,
                              const float* __restrict__ dinv,
                              const float* __restrict__ bias, int n) {
    int c    = (blockIdx.x * blockDim.x + threadIdx.x) >> 5;
    int lane = threadIdx.x & 31;
    if (c >= n) return;
    int s = off[c], e = off[c + 1];
    float dc = dinv[c];

    const float4* A4 = (const float4*)A;
    float ax0 = 0.f, ay0 = 0.f, az0 = 0.f, aw0 = 0.f;
    float ax1 = 0.f, ay1 = 0.f, az1 = 0.f, aw1 = 0.f;

    for (int base = s; base < e; base += 32) {
        int idx = base + lane;
        int r = 0; float dr = 0.f;
        if (idx < e) { r = srcid[idx]; dr = srcdn[idx]; }
        int m = min(32, e - base);
        int k = 0;
        for (; k + 4 <= m; k += 4) {
            int   r0 = __shfl_sync(0xffffffffu, r, k);
            int   r1 = __shfl_sync(0xffffffffu, r, k + 1);
            int   r2 = __shfl_sync(0xffffffffu, r, k + 2);
            int   r3 = __shfl_sync(0xffffffffu, r, k + 3);
            float d0 = __shfl_sync(0xffffffffu, dr, k);
            float d1 = __shfl_sync(0xffffffffu, dr, k + 1);
            float d2 = __shfl_sync(0xffffffffu, dr, k + 2);
            float d3 = __shfl_sync(0xffffffffu, dr, k + 3);
            float4 v0 = A4[(size_t)r0 * 32 + lane];
            float4 v1 = A4[(size_t)r1 * 32 + lane];
            float4 v2 = A4[(size_t)r2 * 32 + lane];
            float4 v3 = A4[(size_t)r3 * 32 + lane];
            ax0 += d0 * v0.x; ay0 += d0 * v0.y; az0 += d0 * v0.z; aw0 += d0 * v0.w;
            ax1 += d1 * v1.x; ay1 += d1 * v1.y; az1 += d1 * v1.z; aw1 += d1 * v1.w;
            ax0 += d2 * v2.x; ay0 += d2 * v2.y; az0 += d2 * v2.z; aw0 += d2 * v2.w;
            ax1 += d3 * v3.x; ay1 += d3 * v3.y; az1 += d3 * v3.z; aw1 += d3 * v3.w;
        }
        for (; k < m; ++k) {
            int   r0 = __shfl_sync(0xffffffffu, r, k);
            float d0 = __shfl_sync(0xffffffffu, dr, k);
            float4 v0 = A4[(size_t)r0 * 32 + lane];
            ax0 += d0 * v0.x; ay0 += d0 * v0.y; az0 += d0 * v0.z; aw0 += d0 * v0.w;
        }
    }
    float4 b = ((const float4*)bias)[lane];
    float4 o;
    o.x = fmaxf(b.x + dc * (ax0 + ax1), 0.f);
    o.y = fmaxf(b.y + dc * (ay0 + ay1), 0.f);
    o.z = fmaxf(b.z + dc * (az0 + az1), 0.f);
    o.w = fmaxf(b.w + dc * (aw0 + aw1), 0.f);
    ((float4*)dst)[(size_t)c * 32 + lane] = o;
}

// ---------------------------------------------------------------------------
// Register-tiled GEMM: C[n][COUT] = A[n][128] @ W[128][COUT] (+ bias).
// Block tile 128 rows x 64 cols, 256 threads, 4x8 micro-tile/thread, K by 32.
// Operands pre-packed in smem as f32x2 k-pairs. W is split into 4 pair-arrays
// so each of the 4 w LDS.128 has a 128B contiguous warp footprint (1 wavefront)
// -> inner loop = 6 LDS wavefronts vs 16 FMA cycles per k2 (fma-bound).
// ---------------------------------------------------------------------------
template <int COUT, bool BIAS>
__global__ __launch_bounds__(256, 2)
void gemm_kernel(const float* __restrict__ A, const float* __restrict__ W,
                 const float* __restrict__ bias, float* __restrict__ C, int n) {
    __shared__ unsigned long long As2[16][130];   // [k2][row] {A[row][2k2],A[row][2k2+1]}
    __shared__ unsigned long long Ws[4][16][18];  // [pair][k2][tc*2+e] -> col tc*8+pair*2+e

    int tid = threadIdx.x;
    int tc  = tid & 7;    // col group: 8 cols
    int tr  = tid >> 3;   // row group: 4 rows
    int r0  = blockIdx.x * 128;
    int c0  = blockIdx.y * 64;

    unsigned long long acc[4][8];
#pragma unroll
    for (int r = 0; r < 4; ++r)
#pragma unroll
        for (int c = 0; c < 8; ++c) acc[r][c] = 0ull;

    const float4* A4 = (const float4*)A;

    for (int kc = 0; kc < 4; ++kc) {
        // stage A chunk (transpose+pack): coalesced f4 reads
        {
            int q   = tid & 7;    // float4 index within 32-k chunk -> k2 = 2q, 2q+1
            int row = tid >> 3;   // 0..31
#pragma unroll
            for (int i = 0; i < 4; ++i) {
                int rr = row + i * 32;
                int gr = r0 + rr;
                float4 v = make_float4(0.f, 0.f, 0.f, 0.f);
                if (gr < n) v = A4[(size_t)gr * 32 + kc * 8 + q];
                unsigned long long p0, p1;
                PACK2(p0, v.x, v.y);
                PACK2(p1, v.z, v.w);
                As2[2 * q    ][rr] = p0;
                As2[2 * q + 1][rr] = p1;
            }
        }
        // stage W chunk into 4 pair-arrays: one (k2, 4-col group) per thread
        {
            int cg = tid & 15;
            int k2 = tid >> 4;
            int gk = kc * 32 + 2 * k2;
            float4 wa = ((const float4*)(W + (size_t)gk * COUT))[(c0 >> 2) + cg];
            float4 wb = ((const float4*)(W + (size_t)(gk + 1) * COUT))[(c0 >> 2) + cg];
            unsigned long long p0, p1, p2, p3;
            PACK2(p0, wa.x, wb.x); PACK2(p1, wa.y, wb.y);
            PACK2(p2, wa.z, wb.z); PACK2(p3, wa.w, wb.w);
            int pa  = (cg & 1) * 2;       // pair index of first two cols
            int dst = (cg >> 1) * 2;      // tc*2 within pair-array
            *(ulonglong2*)&Ws[pa    ][k2][dst] = make_ulonglong2(p0, p1);
            *(ulonglong2*)&Ws[pa + 1][k2][dst] = make_ulonglong2(p2, p3);
        }
        __syncthreads();

#pragma unroll
        for (int k2 = 0; k2 < 16; ++k2) {
            unsigned long long a[4], w[8];
            ulonglong2 t;
            const ulonglong2* ap = (const ulonglong2*)&As2[k2][tr * 4];
            t = ap[0]; a[0] = t.x; a[1] = t.y;
            t = ap[1]; a[2] = t.x; a[3] = t.y;
#pragma unroll
            for (int p = 0; p < 4; ++p) {
                t = *(const ulonglong2*)&Ws[p][k2][tc * 2];
                w[2 * p] = t.x; w[2 * p + 1] = t.y;
            }
#pragma unroll
            for (int r = 0; r < 4; ++r)
#pragma unroll
                for (int c = 0; c < 8; ++c)
                    FMA_F32X2(acc[r][c], a[r], w[c]);
        }
        __syncthreads();
    }

    // epilogue: reduce k-even/odd partials, add bias, vector stores
#pragma unroll
    for (int r = 0; r < 4; ++r) {
        int gr = r0 + tr * 4 + r;
        if (gr >= n) break;
        float v[8];
#pragma unroll
        for (int c = 0; c < 8; ++c) {
            float lo, hi;
            UNPACK2(lo, hi, acc[r][c]);
            v[c] = lo + hi;
        }
        if (BIAS) {
            const float4* b4 = (const float4*)(bias + c0 + tc * 8);
            float4 ba = b4[0], bb = b4[1];
            v[0] += ba.x; v[1] += ba.y; v[2] += ba.z; v[3] += ba.w;
            v[4] += bb.x; v[5] += bb.y; v[6] += bb.z; v[7] += bb.w;
        }
        float4* cp = (float4*)(C + (size_t)gr * COUT + c0 + tc * 8);
        cp[0] = make_float4(v[0], v[1], v[2], v[3]);
        cp[1] = make_float4(v[4], v[5], v[6], v[7]);
    }
}

// ---------------------------------------------------------------------------
// Launch. Inputs: x, edge_index, W1, b1, W2, b2, Wl, bl. Output: [n, 64] f32.
// ---------------------------------------------------------------------------
extern "C" void kernel_launch(void* const* d_in, const int* in_sizes, int n_in,
                              void* d_out, int out_size) {
    const float* x  = (const float*)d_in[0];
    const void*  ei = d_in[1];
    const float* W1 = (const float*)d_in[2];
    const float* b1 = (const float*)d_in[3];
    const float* W2 = (const float*)d_in[4];
    const float* b2 = (const float*)d_in[5];
    const float* Wl = (const float*)d_in[6];
    const float* bl = (const float*)d_in[7];
    float* out = (float*)d_out;

    int n = in_sizes[0] / 128;   // 50000
    int E = in_sizes[1] / 2;     // 640000

    float *dinv, *bufA, *bufB, *srcdn;
    int *cnt, *incl, *bsum, *off, *cursor, *srcid;
    cudaGetSymbolAddress((void**)&dinv,   g_dinv);
    cudaGetSymbolAddress((void**)&bufA,   g_bufA);
    cudaGetSymbolAddress((void**)&bufB,   g_bufB);
    cudaGetSymbolAddress((void**)&cnt,    g_cnt);
    cudaGetSymbolAddress((void**)&incl,   g_incl);
    cudaGetSymbolAddress((void**)&bsum,   g_bsum);
    cudaGetSymbolAddress((void**)&off,    g_off);
    cudaGetSymbolAddress((void**)&cursor, g_cursor);
    cudaGetSymbolAddress((void**)&srcid,  g_srcid);
    cudaGetSymbolAddress((void**)&srcdn,  g_srcdn);

    int nb256 = (n + 255) / 256;      // 196
    int EN = E + n;
    int rowb = (n + 127) / 128;       // 391
    dim3 grid128(rowb, 2);            // COUT=128: 2 col blocks of 64
    dim3 grid64(rowb, 1);
    int gather_blocks = (n + 7) / 8;

    // CSR build interleaved; gemm1 (independent of CSR) placed 4th so the
    // ncu capture window lands on it.
    detect_dtype_kernel<<<1, 32>>>((const int*)ei);
    cnt_init_kernel<<<nb256, 256>>>(cnt, n);
    cnt_count_kernel<<<(E + 255) / 256, 256>>>(cnt, ei, E);
    gemm_kernel<128, false><<<grid128, 256>>>(x, W1, nullptr, bufA, n);
    scan1_kernel<<<nb256, 256>>>(cnt, incl, bsum, n);
    scan2_kernel<<<1, 256>>>(bsum, nb256);
    scan3_kernel<<<nb256, 256>>>(incl, bsum, cnt, off, cursor, dinv, n);
    fill_kernel<<<(EN + 255) / 256, 256>>>(cursor, srcid, srcdn, dinv, ei, E, n);

    // Layer 1 aggregate: h1 = relu( Agg(x @ W1) + b1 )
    gather_kernel<<<gather_blocks, 256>>>(bufA, bufB, srcid, srcdn, off, dinv, b1, n);

    // Layer 2: h2 = relu( Agg(h1 @ W2) + b2 )
    gemm_kernel<128, false><<<grid128, 256>>>(bufB, W2, nullptr, bufA, n);
    gather_kernel<<<gather_blocks, 256>>>(bufA, bufB, srcid, srcdn, off, dinv, b2, n);

    // Head: out = h2 @ Wl + bl
    gemm_kernel<64, true><<<grid64, 256>>>(bufB, Wl, bl, out, n);
}